// round 14
// baseline (speedup 1.0000x reference)
#include <cuda_runtime.h>
#include <cuda_fp16.h>
#include <cstdint>

// ---------------------------------------------------------------------------
// Problem constants
// ---------------------------------------------------------------------------
#define BATCH      4096
#define INPUT_DIM  1024
#define NUM_TREES  64
#define N_INTERNAL 63
#define N_LEAVES   64
#define LEAF_DIMS  10
#define NCOLS      (N_INTERNAL * NUM_TREES)   // 4032

// Fused GEMM+tree tiling: CTA 256 rows x 64 cols (= one tree)
#define BM       256
#define BK       32                    // fp16 elems per K-chunk
#define NCHUNKS  (INPUT_DIM / BK)      // 32
#define STAGES   4
#define ROWB     80                    // 64 data bytes + 16 pad (conflict-free ldmatrix)
#define ATILEB   (256 * ROWB)          // 20480
#define BTILEB   (64 * ROWB)           // 5120
#define STAGE_BYTES (ATILEB + BTILEB)  // 25600
#define GEMM_SMEM   (STAGES * STAGE_BYTES)  // 102400 -> 2 CTAs/SM
#define GATE_PAD 65                    // smem gates row stride (odd -> conflict-free)

// ---------------------------------------------------------------------------
// Device scratch (no cudaMalloc allowed)
// ---------------------------------------------------------------------------
__device__ __half  g_xh[(size_t)BATCH * INPUT_DIM];
__device__ __half  g_wh[(size_t)NCOLS * INPUT_DIM];
__device__ float   g_lwt[NUM_TREES * N_LEAVES * LEAF_DIMS];          // [t][l*10+d]
__device__ float   g_part[(size_t)NUM_TREES * BATCH * LEAF_DIMS];    // 10.5 MB

// ---------------------------------------------------------------------------
// PTX helpers (base-sm_100-safe: cp.async, ldmatrix, mma.sync)
// ---------------------------------------------------------------------------
__device__ __forceinline__ uint32_t smem_u32(const void* p) {
    uint32_t a;
    asm("{ .reg .u64 t; cvta.to.shared.u64 t, %1; cvt.u32.u64 %0, t; }" : "=r"(a) : "l"(p));
    return a;
}

__device__ __forceinline__ void cp16(uint32_t s, const void* g, uint32_t srcBytes) {
    asm volatile("cp.async.cg.shared.global [%0], [%1], 16, %2;"
                 :: "r"(s), "l"(__cvta_generic_to_global(g)), "r"(srcBytes));
}
#define CP_COMMIT() asm volatile("cp.async.commit_group;" ::: "memory")
#define CP_WAIT3()  asm volatile("cp.async.wait_group 3;"  ::: "memory")
#define CP_WAIT0()  asm volatile("cp.async.wait_group 0;"  ::: "memory")

#define LDSM_X4(r, addr)                                                        \
    asm volatile("ldmatrix.sync.aligned.m8n8.x4.shared.b16 {%0,%1,%2,%3}, [%4];"\
                 : "=r"((r)[0]), "=r"((r)[1]), "=r"((r)[2]), "=r"((r)[3])       \
                 : "r"(addr))

__device__ __forceinline__ void mma16816(float* c, const uint32_t* a,
                                         uint32_t b0, uint32_t b1) {
    asm volatile(
        "mma.sync.aligned.m16n8k16.row.col.f32.f16.f16.f32 "
        "{%0,%1,%2,%3}, {%4,%5,%6,%7}, {%8,%9}, {%0,%1,%2,%3};"
        : "+f"(c[0]), "+f"(c[1]), "+f"(c[2]), "+f"(c[3])
        : "r"(a[0]), "r"(a[1]), "r"(a[2]), "r"(a[3]), "r"(b0), "r"(b1));
}

// ---------------------------------------------------------------------------
// Kernel 0a: convert fp32 -> fp16
// ---------------------------------------------------------------------------
__global__ void conv_kernel(const float* __restrict__ src,
                            __half* __restrict__ dst, int n4)
{
    int i = blockIdx.x * blockDim.x + threadIdx.x;
    if (i >= n4) return;
    float4 v = reinterpret_cast<const float4*>(src)[i];
    reinterpret_cast<__half2*>(dst)[2 * i]     =
        __halves2half2(__float2half(v.x), __float2half(v.y));
    reinterpret_cast<__half2*>(dst)[2 * i + 1] =
        __halves2half2(__float2half(v.z), __float2half(v.w));
}

// ---------------------------------------------------------------------------
// Kernel 0b: transpose leaf_w (l,d,t) -> [t][l*10+d] (contiguous per tree)
// ---------------------------------------------------------------------------
__global__ void transpose_lw_kernel(const float* __restrict__ lw,
                                    float* __restrict__ lwt)
{
    int o = blockIdx.x * blockDim.x + threadIdx.x;
    if (o >= NUM_TREES * N_LEAVES * LEAF_DIMS) return;
    const int t = o / (N_LEAVES * LEAF_DIMS);
    const int r = o % (N_LEAVES * LEAF_DIMS);
    lwt[o] = lw[r * NUM_TREES + t];
}

// ---------------------------------------------------------------------------
// Kernel 1: fused fp16 GEMM + sigmoid + tree expansion + leaf contraction.
// CTA = 256 batch rows x 1 tree (64 gate cols, col 63 zero pad).
// 8 warps (4M x 1... wm 0..3 over 64-row slabs, wn 0..1 over 32-col slabs).
// Emits per-tree partial outputs g_part[tree][row][10].
// ---------------------------------------------------------------------------
struct LoadCtx {
    const __half *ax, *bw;
    uint32_t bBytes;
};

__device__ __forceinline__ void issue_stage(uint32_t sb, int stage, int kt,
                                            const LoadCtx& L, int tid)
{
    const uint32_t s = sb + stage * STAGE_BYTES;
    const uint32_t aOff = s + tid * ROWB;
    #pragma unroll
    for (int q = 0; q < 4; ++q)
        cp16(aOff + q * 16, L.ax + kt + q * 8, 16);
    if (tid < 64) {
        const uint32_t bOff = s + ATILEB + tid * ROWB;
        #pragma unroll
        for (int q = 0; q < 4; ++q)
            cp16(bOff + q * 16, L.bw + kt + q * 8, L.bBytes);
    }
}

__global__ void __launch_bounds__(256, 2)
gemm_tree_kernel(const float* __restrict__ bias)
{
    extern __shared__ char smem[];
    const uint32_t sb = smem_u32(smem);
    const int tid  = threadIdx.x;
    const int lane = tid & 31;
    const int wid  = tid >> 5;
    const int wm   = wid & 3;          // M warp (0..3), 64 rows each
    const int wn   = wid >> 2;         // N warp (0..1), 32 cols each

    const int rowBase = blockIdx.x * BM;
    const int tree    = blockIdx.y;

    LoadCtx L;
    {
        L.ax = g_xh + (size_t)(rowBase + tid) * INPUT_DIM;
        const int bRow = (tid < 63) ? tid : 62;          // clamp (row 63 zero-filled)
        L.bw = g_wh + (size_t)(bRow * NUM_TREES + tree) * INPUT_DIM;
        L.bBytes = (tid < 63) ? 16u : 0u;
    }

    const int l8  = lane & 7;
    const int sel = lane >> 3;
    const uint32_t aAddr = (uint32_t)((wm * 64 + (sel & 1) * 8 + l8) * ROWB + (sel >> 1) * 16);
    const uint32_t bAddr = (uint32_t)(ATILEB + (wn * 32 + (sel >> 1) * 8 + l8) * ROWB + (sel & 1) * 16);

    float acc[4][4][4];
    #pragma unroll
    for (int mt = 0; mt < 4; ++mt)
        #pragma unroll
        for (int nt = 0; nt < 4; ++nt)
            #pragma unroll
            for (int e = 0; e < 4; ++e) acc[mt][nt][e] = 0.0f;

    issue_stage(sb, 0, 0 * BK, L, tid);  CP_COMMIT();
    issue_stage(sb, 1, 1 * BK, L, tid);  CP_COMMIT();
    issue_stage(sb, 2, 2 * BK, L, tid);  CP_COMMIT();

    for (int ch = 0; ch < NCHUNKS; ++ch) {
        const int nc = ch + 3;
        if (nc < NCHUNKS) issue_stage(sb, nc % STAGES, nc * BK, L, tid);
        CP_COMMIT();
        CP_WAIT3();
        __syncthreads();

        const uint32_t st = sb + (ch % STAGES) * STAGE_BYTES;
        const uint32_t aT = st + aAddr;
        const uint32_t bT = st + bAddr;

        #pragma unroll
        for (int h = 0; h < 2; ++h) {
            uint32_t bh[2][4];
            #pragma unroll
            for (int np = 0; np < 2; ++np)
                LDSM_X4(bh[np], bT + np * 16 * ROWB + h * 32);
            #pragma unroll
            for (int mt = 0; mt < 4; ++mt) {
                uint32_t ah[4];
                LDSM_X4(ah, aT + mt * 16 * ROWB + h * 32);
                #pragma unroll
                for (int nt = 0; nt < 4; ++nt) {
                    const uint32_t* Bp = &bh[nt >> 1][(nt & 1) * 2];
                    mma16816(acc[mt][nt], ah, Bp[0], Bp[1]);
                }
            }
        }
        __syncthreads();
    }

    // --- epilogue phase 1: drain pipeline, reuse smem for gates + leaf_w ---
    CP_WAIT0();
    __syncthreads();
    float* gates = reinterpret_cast<float*>(smem);             // [256][GATE_PAD]
    float* slw   = reinterpret_cast<float*>(smem) + 256 * GATE_PAD;  // [640]

    // cache this tree's leaf weights (contiguous in g_lwt)
    {
        const float* src = g_lwt + tree * (N_LEAVES * LEAF_DIMS);
        #pragma unroll
        for (int i = tid; i < N_LEAVES * LEAF_DIMS; i += 256)
            slw[i] = __ldg(src + i);
    }

    // write sigmoid gates to smem (rows 0..255, gate cols 0..62; col 63 dummy)
    {
        const int r0 = wm * 64 + (lane >> 2);
        const int c0 = wn * 32 + (lane & 3) * 2;
        #pragma unroll
        for (int nt = 0; nt < 4; ++nt) {
            const int c = c0 + nt * 8;             // even, <= 62
            const float b0v = __ldg(bias + c * NUM_TREES + tree);
            const float b1v = (c + 1 < N_INTERNAL)
                              ? __ldg(bias + (c + 1) * NUM_TREES + tree) : 0.0f;
            #pragma unroll
            for (int mt = 0; mt < 4; ++mt) {
                const int r = r0 + mt * 16;
                gates[r * GATE_PAD + c]     = 1.0f / (1.0f + __expf(-(acc[mt][nt][0] + b0v)));
                gates[r * GATE_PAD + c + 1] = 1.0f / (1.0f + __expf(-(acc[mt][nt][1] + b1v)));
                gates[(r + 8) * GATE_PAD + c]     = 1.0f / (1.0f + __expf(-(acc[mt][nt][2] + b0v)));
                gates[(r + 8) * GATE_PAD + c + 1] = 1.0f / (1.0f + __expf(-(acc[mt][nt][3] + b1v)));
            }
        }
    }
    __syncthreads();

    // --- epilogue phase 2: per-thread tree expansion for row `tid` ---
    const float* gr = gates + tid * GATE_PAD;

    float pr[32];
    pr[0] = 1.0f;
    #pragma unroll
    for (int L5 = 0; L5 < 5; ++L5) {
        const int num  = 1 << L5;
        const int base = num - 1;
        #pragma unroll
        for (int i = num - 1; i >= 0; --i) {
            const float g = gr[base + i];
            const float p = pr[i];
            pr[2 * i]     = p * g;
            pr[2 * i + 1] = p * (1.0f - g);
        }
    }

    float oacc[LEAF_DIMS];
    #pragma unroll
    for (int d = 0; d < LEAF_DIMS; ++d) oacc[d] = 0.0f;
    #pragma unroll
    for (int i = 0; i < 32; ++i) {
        const float g  = gr[31 + i];
        const float p  = pr[i];
        const float p0 = p * g;
        const float p1 = p - p0;
        const float* w0 = slw + (2 * i)     * LEAF_DIMS;
        const float* w1 = slw + (2 * i + 1) * LEAF_DIMS;
        #pragma unroll
        for (int d = 0; d < LEAF_DIMS; ++d)
            oacc[d] = fmaf(p0, w0[d], fmaf(p1, w1[d], oacc[d]));
    }

    // write per-tree partials (coalesced-ish: 40B per consecutive thread)
    float* dst = g_part + ((size_t)tree * BATCH + rowBase + tid) * LEAF_DIMS;
    #pragma unroll
    for (int q = 0; q < 5; ++q)
        *reinterpret_cast<float2*>(dst + 2 * q) =
            make_float2(oacc[2 * q], oacc[2 * q + 1]);
}

// ---------------------------------------------------------------------------
// Kernel 2: reduce partials over trees: out[i] = sum_t part[t][i]
// ---------------------------------------------------------------------------
__global__ __launch_bounds__(256)
void reduce_kernel(float* __restrict__ out)
{
    const int i = blockIdx.x * 256 + threadIdx.x;   // < 40960
    float s = 0.0f;
    #pragma unroll 8
    for (int t = 0; t < NUM_TREES; ++t)
        s += __ldg(g_part + (size_t)t * (BATCH * LEAF_DIMS) + i);
    out[i] = s;
}

// ---------------------------------------------------------------------------
extern "C" void kernel_launch(void* const* d_in, const int* in_sizes, int n_in,
                              void* d_out, int out_size)
{
    const float* x      = (const float*)d_in[0];   // (4096, 1024)
    const float* W      = (const float*)d_in[1];   // (63, 64, 1024)
    const float* bias   = (const float*)d_in[2];   // (63, 64)
    const float* leaf_w = (const float*)d_in[3];   // (64, 10, 64)
    float* out = (float*)d_out;                    // (4096, 10)

    cudaFuncSetAttribute(gemm_tree_kernel,
                         cudaFuncAttributeMaxDynamicSharedMemorySize, GEMM_SMEM);

    __half *xh, *wh;
    float *lwt;
    cudaGetSymbolAddress((void**)&xh,  g_xh);
    cudaGetSymbolAddress((void**)&wh,  g_wh);
    cudaGetSymbolAddress((void**)&lwt, g_lwt);

    const int nx4 = BATCH * INPUT_DIM / 4;
    const int nw4 = NCOLS * INPUT_DIM / 4;
    const int nlw = NUM_TREES * N_LEAVES * LEAF_DIMS;
    conv_kernel<<<(nx4 + 255) / 256, 256>>>(x, xh, nx4);
    conv_kernel<<<(nw4 + 255) / 256, 256>>>(W, wh, nw4);
    transpose_lw_kernel<<<(nlw + 255) / 256, 256>>>(leaf_w, lwt);

    dim3 ggrid(BATCH / BM, NUM_TREES);   // (16, 64)
    gemm_tree_kernel<<<ggrid, 256, GEMM_SMEM>>>(bias);

    reduce_kernel<<<(BATCH * LEAF_DIMS) / 256, 256>>>(out);
}

// round 16
// speedup vs baseline: 1.2890x; 1.2890x over previous
#include <cuda_runtime.h>
#include <cuda_fp16.h>
#include <cstdint>

// ---------------------------------------------------------------------------
// Problem constants
// ---------------------------------------------------------------------------
#define BATCH      4096
#define INPUT_DIM  1024
#define NUM_TREES  64
#define N_INTERNAL 63
#define N_LEAVES   64
#define LEAF_DIMS  10
#define NCOLS      (N_INTERNAL * NUM_TREES)   // 4032

// GEMM tiling: CTA 128x128, 8 warps (2M x 4N), warp tile 64x32
#define BM       128
#define BN       128
#define BK       32                    // fp16 elems per K-chunk
#define NCHUNKS  (INPUT_DIM / BK)      // 32
#define STAGES   4
#define ROWB     80                    // 64 data bytes + 16 pad (conflict-free ldmatrix)
#define TILEB    (128 * ROWB)          // 10240 per tile
#define STAGE_BYTES (2 * TILEB)        // 20480 (X, W)
#define GEMM_SMEM   (STAGES * STAGE_BYTES)  // 81920 -> 2 CTAs/SM (160KB)

// ---------------------------------------------------------------------------
// Device scratch (no cudaMalloc allowed)
// ---------------------------------------------------------------------------
__device__ float   g_gates[(size_t)BATCH * NCOLS];      // 66 MB
__device__ __half  g_xh[(size_t)BATCH * INPUT_DIM];
__device__ __half  g_wh[(size_t)NCOLS * INPUT_DIM];
// leaf_w transposed: [leaf][d-pair][tree] as float2 -> coalesced float2 loads
__device__ __align__(8) float2 g_lwt[N_LEAVES * (LEAF_DIMS / 2) * NUM_TREES];

// ---------------------------------------------------------------------------
// PTX helpers (base-sm_100-safe: cp.async, ldmatrix, mma.sync)
// ---------------------------------------------------------------------------
__device__ __forceinline__ uint32_t smem_u32(const void* p) {
    uint32_t a;
    asm("{ .reg .u64 t; cvta.to.shared.u64 t, %1; cvt.u32.u64 %0, t; }" : "=r"(a) : "l"(p));
    return a;
}

// .cg: bypass L1, stage via L2 only (16B transfers)
__device__ __forceinline__ void cp16(uint32_t s, const void* g, uint32_t srcBytes) {
    asm volatile("cp.async.cg.shared.global [%0], [%1], 16, %2;"
                 :: "r"(s), "l"(__cvta_generic_to_global(g)), "r"(srcBytes));
}
#define CP_COMMIT() asm volatile("cp.async.commit_group;" ::: "memory")
#define CP_WAIT3()  asm volatile("cp.async.wait_group 3;"  ::: "memory")

#define LDSM_X4(r, addr)                                                        \
    asm volatile("ldmatrix.sync.aligned.m8n8.x4.shared.b16 {%0,%1,%2,%3}, [%4];"\
                 : "=r"((r)[0]), "=r"((r)[1]), "=r"((r)[2]), "=r"((r)[3])       \
                 : "r"(addr))

__device__ __forceinline__ void mma16816(float* c, const uint32_t* a,
                                         uint32_t b0, uint32_t b1) {
    asm volatile(
        "mma.sync.aligned.m16n8k16.row.col.f32.f16.f16.f32 "
        "{%0,%1,%2,%3}, {%4,%5,%6,%7}, {%8,%9}, {%0,%1,%2,%3};"
        : "+f"(c[0]), "+f"(c[1]), "+f"(c[2]), "+f"(c[3])
        : "r"(a[0]), "r"(a[1]), "r"(a[2]), "r"(a[3]), "r"(b0), "r"(b1));
}

// ---------------------------------------------------------------------------
// Kernel 0a: convert fp32 -> fp16 (used for both X and W)
// ---------------------------------------------------------------------------
__global__ void conv_kernel(const float* __restrict__ src,
                            __half* __restrict__ dst, int n4)
{
    int i = blockIdx.x * blockDim.x + threadIdx.x;
    if (i >= n4) return;
    float4 v = reinterpret_cast<const float4*>(src)[i];
    reinterpret_cast<__half2*>(dst)[2 * i]     =
        __halves2half2(__float2half(v.x), __float2half(v.y));
    reinterpret_cast<__half2*>(dst)[2 * i + 1] =
        __halves2half2(__float2half(v.z), __float2half(v.w));
}

// ---------------------------------------------------------------------------
// Kernel 0b: transpose leaf_w (l,d,t) -> float2[(l*5+dp)*64 + t] = (w_d, w_d+1)
// ---------------------------------------------------------------------------
__global__ void transpose_lw_kernel(const float* __restrict__ lw,
                                    float2* __restrict__ lwt)
{
    int o = blockIdx.x * blockDim.x + threadIdx.x;
    if (o >= N_LEAVES * 5 * NUM_TREES) return;
    const int l  = o / (5 * NUM_TREES);
    const int r  = o % (5 * NUM_TREES);
    const int dp = r / NUM_TREES;
    const int t  = r % NUM_TREES;
    float2 v;
    v.x = lw[(l * LEAF_DIMS + 2 * dp)     * NUM_TREES + t];
    v.y = lw[(l * LEAF_DIMS + 2 * dp + 1) * NUM_TREES + t];
    lwt[o] = v;
}

// ---------------------------------------------------------------------------
// Kernel 1: fp16 mma.sync GEMM (single term, fp32 accumulate), fused
// bias+sigmoid epilogue. CTA 128x128, 8 warps (2Mx4N, 64x32 each),
// 4-stage cp.async.cg, 2 CTAs/SM.   (byte-identical to round 13)
// ---------------------------------------------------------------------------
struct LoadCtx {
    const __half *ax, *bw;
    uint32_t wOff;
    uint32_t bBytes;
};

__device__ __forceinline__ void issue_stage(uint32_t sb, int stage, int kt,
                                            const LoadCtx& L)
{
    const uint32_t s = sb + stage * STAGE_BYTES + L.wOff;
    cp16(s +          0, L.ax + kt,     16);
    cp16(s +         16, L.ax + kt + 8, 16);
    cp16(s + TILEB +  0, L.bw + kt,     L.bBytes);
    cp16(s + TILEB + 16, L.bw + kt + 8, L.bBytes);
}

__global__ void __launch_bounds__(256, 2)
gemm_mma_kernel(const float* __restrict__ bias)
{
    extern __shared__ char smem[];
    const uint32_t sb = smem_u32(smem);
    const int tid  = threadIdx.x;
    const int lane = tid & 31;
    const int wid  = tid >> 5;
    const int wm   = wid & 1;          // M warp (0..1), 64 rows each
    const int wn   = wid >> 1;         // N warp (0..3), 32 cols each

    const int rowBase = blockIdx.y * BM;
    const int colBase = blockIdx.x * BN;

    LoadCtx L;
    {
        const int ldRow = tid >> 1;
        const int ldSeg = (tid & 1) * 2;
        L.ax = g_xh + (size_t)(rowBase + ldRow) * INPUT_DIM + ldSeg * 8;
        L.bw = g_wh + (size_t)(colBase + ldRow) * INPUT_DIM + ldSeg * 8;
        L.wOff   = (uint32_t)(ldRow * ROWB + ldSeg * 16);
        L.bBytes = ((colBase + ldRow) < NCOLS) ? 16u : 0u;
    }

    const int l8  = lane & 7;
    const int sel = lane >> 3;
    const uint32_t aAddr = (uint32_t)((wm * 64 + (sel & 1) * 8 + l8) * ROWB + (sel >> 1) * 16);
    const uint32_t bAddr = (uint32_t)((wn * 32 + (sel >> 1) * 8 + l8) * ROWB + (sel & 1) * 16);

    float acc[4][4][4];
    #pragma unroll
    for (int mt = 0; mt < 4; ++mt)
        #pragma unroll
        for (int nt = 0; nt < 4; ++nt)
            #pragma unroll
            for (int e = 0; e < 4; ++e) acc[mt][nt][e] = 0.0f;

    issue_stage(sb, 0, 0 * BK, L);  CP_COMMIT();
    issue_stage(sb, 1, 1 * BK, L);  CP_COMMIT();
    issue_stage(sb, 2, 2 * BK, L);  CP_COMMIT();

    for (int ch = 0; ch < NCHUNKS; ++ch) {
        const int nc = ch + 3;
        if (nc < NCHUNKS) issue_stage(sb, nc % STAGES, nc * BK, L);
        CP_COMMIT();
        CP_WAIT3();
        __syncthreads();

        const uint32_t st = sb + (ch % STAGES) * STAGE_BYTES;
        const uint32_t aT = st + aAddr;
        const uint32_t bT = st + TILEB + bAddr;

        #pragma unroll
        for (int h = 0; h < 2; ++h) {
            uint32_t bh[2][4];
            #pragma unroll
            for (int np = 0; np < 2; ++np)
                LDSM_X4(bh[np], bT + np * 16 * ROWB + h * 32);
            #pragma unroll
            for (int mt = 0; mt < 4; ++mt) {
                uint32_t ah[4];
                LDSM_X4(ah, aT + mt * 16 * ROWB + h * 32);
                #pragma unroll
                for (int nt = 0; nt < 4; ++nt) {
                    const uint32_t* Bp = &bh[nt >> 1][(nt & 1) * 2];
                    mma16816(acc[mt][nt], ah, Bp[0], Bp[1]);
                }
            }
        }
        __syncthreads();
    }

    // epilogue: bias + sigmoid from register accumulators
    const int cRow  = rowBase + wm * 64 + (lane >> 2);
    const int cCol0 = colBase + wn * 32 + (lane & 3) * 2;
    #pragma unroll
    for (int nt = 0; nt < 4; ++nt) {
        const int c = cCol0 + nt * 8;
        if (c >= NCOLS) continue;
        const float2 bv = *reinterpret_cast<const float2*>(bias + c);
        #pragma unroll
        for (int mt = 0; mt < 4; ++mt) {
            const int r0 = cRow + mt * 16;
            float2 g0, g1;
            g0.x = 1.0f / (1.0f + __expf(-(acc[mt][nt][0] + bv.x)));
            g0.y = 1.0f / (1.0f + __expf(-(acc[mt][nt][1] + bv.y)));
            g1.x = 1.0f / (1.0f + __expf(-(acc[mt][nt][2] + bv.x)));
            g1.y = 1.0f / (1.0f + __expf(-(acc[mt][nt][3] + bv.y)));
            *reinterpret_cast<float2*>(&g_gates[(size_t)r0 * NCOLS + c])       = g0;
            *reinterpret_cast<float2*>(&g_gates[(size_t)(r0 + 8) * NCOLS + c]) = g1;
        }
    }
}

// ---------------------------------------------------------------------------
// Kernel 2: tree expansion + leaf contraction, MLP-maximized.
// 256 threads = 4 batch rows x 64 trees. ALL 63 gates loaded into registers
// up front (independent __ldg -> ~60 outstanding loads/thread), then
// expansion/contraction from registers. launch_bounds(256,2) caps regs at 128
// (occupancy ~50%, latency hidden by MLP instead of warp count).
// ---------------------------------------------------------------------------
__global__ __launch_bounds__(256, 2)
void tree_kernel(float* __restrict__ out)
{
    const int tid  = threadIdx.x;
    const int rg   = tid >> 6;          // row-in-block 0..3
    const int t    = tid & 63;          // tree id
    const int lane = tid & 31;
    const int wip  = (tid >> 5) & 1;    // warp-in-rowgroup

    const int b = blockIdx.x * 4 + rg;
    const float* __restrict__ gb  = g_gates + (size_t)b * NCOLS + t;
    const float2* __restrict__ lw = g_lwt;

    __shared__ float spart[4][2][LEAF_DIMS];

    // ---- batch-load ALL 63 gates (independent, coalesced, high MLP) ----
    float g[N_INTERNAL];
    #pragma unroll
    for (int n = 0; n < N_INTERNAL; ++n)
        g[n] = __ldg(gb + n * NUM_TREES);

    // ---- levels 0..4: expand to 32 probs in registers ----
    float pr[32];
    pr[0] = 1.0f;
    #pragma unroll
    for (int L = 0; L < 5; ++L) {
        const int num  = 1 << L;
        const int base = num - 1;
        #pragma unroll
        for (int i = num - 1; i >= 0; --i) {
            const float gv = g[base + i];
            const float p  = pr[i];
            pr[2 * i]     = p * gv;
            pr[2 * i + 1] = p * (1.0f - gv);
        }
    }

    // ---- level 5 fused into contraction ----
    float acc[LEAF_DIMS];
    #pragma unroll
    for (int d = 0; d < LEAF_DIMS; ++d) acc[d] = 0.0f;
    #pragma unroll
    for (int i = 0; i < 32; ++i) {
        const float gv = g[31 + i];
        const float p  = pr[i];
        const float p0 = p * gv;
        const float p1 = p - p0;
        const int base0 = (2 * i)     * 5 * NUM_TREES + t;
        const int base1 = (2 * i + 1) * 5 * NUM_TREES + t;
        #pragma unroll
        for (int dp = 0; dp < 5; ++dp) {
            const float2 w0 = __ldg(lw + base0 + dp * NUM_TREES);
            const float2 w1 = __ldg(lw + base1 + dp * NUM_TREES);
            acc[2 * dp]     = fmaf(p0, w0.x, fmaf(p1, w1.x, acc[2 * dp]));
            acc[2 * dp + 1] = fmaf(p0, w0.y, fmaf(p1, w1.y, acc[2 * dp + 1]));
        }
    }

    // ---- reduce over 64 trees ----
    #pragma unroll
    for (int d = 0; d < LEAF_DIMS; ++d) {
        float v = acc[d];
        #pragma unroll
        for (int off = 16; off > 0; off >>= 1)
            v += __shfl_xor_sync(0xffffffffu, v, off);
        if (lane == 0) spart[rg][wip][d] = v;
    }
    __syncthreads();
    if (tid < 4 * LEAF_DIMS) {
        const int r2 = tid / LEAF_DIMS, d = tid % LEAF_DIMS;
        out[(size_t)(blockIdx.x * 4 + r2) * LEAF_DIMS + d] =
            spart[r2][0][d] + spart[r2][1][d];
    }
}

// ---------------------------------------------------------------------------
extern "C" void kernel_launch(void* const* d_in, const int* in_sizes, int n_in,
                              void* d_out, int out_size)
{
    const float* x      = (const float*)d_in[0];   // (4096, 1024)
    const float* W      = (const float*)d_in[1];   // (63, 64, 1024)
    const float* bias   = (const float*)d_in[2];   // (63, 64)
    const float* leaf_w = (const float*)d_in[3];   // (64, 10, 64)
    float* out = (float*)d_out;                    // (4096, 10)

    cudaFuncSetAttribute(gemm_mma_kernel,
                         cudaFuncAttributeMaxDynamicSharedMemorySize, GEMM_SMEM);

    __half *xh, *wh;
    float2 *lwt;
    cudaGetSymbolAddress((void**)&xh,  g_xh);
    cudaGetSymbolAddress((void**)&wh,  g_wh);
    cudaGetSymbolAddress((void**)&lwt, g_lwt);

    const int nx4 = BATCH * INPUT_DIM / 4;
    const int nw4 = NCOLS * INPUT_DIM / 4;
    const int nlw = N_LEAVES * 5 * NUM_TREES;
    conv_kernel<<<(nx4 + 255) / 256, 256>>>(x, xh, nx4);
    conv_kernel<<<(nw4 + 255) / 256, 256>>>(W, wh, nw4);
    transpose_lw_kernel<<<(nlw + 255) / 256, 256>>>(leaf_w, lwt);

    dim3 ggrid((NCOLS + BN - 1) / BN, BATCH / BM);   // (32, 32)
    gemm_mma_kernel<<<ggrid, 256, GEMM_SMEM>>>(bias);

    tree_kernel<<<BATCH / 4, 256>>>(out);
}